// round 2
// baseline (speedup 1.0000x reference)
#include <cuda_runtime.h>
#include <cstdint>

// Problem constants (fixed by the reference).
static constexpr int NU    = 100000;   // users
static constexpr int NI    = 50000;    // items
static constexpr int D     = 64;       // dim
static constexpr int NP    = 3;        // meta-paths
static constexpr int DEG   = 16;
static constexpr int EU    = NU * DEG; // edges per user path (1.6M)
static constexpr int EI    = NI * DEG; // edges per item path (0.8M)
static constexpr int BATCH = 8192;

static constexpr long long AGG_U_ELEMS = (long long)NP * NU * D; // 19.2M
static constexpr long long AGG_I_ELEMS = (long long)NP * NI * D; //  9.6M

// Scratch: spmm accumulators (pre-W aggregation) + needed-row flags.
__device__ float g_agg_u[(size_t)AGG_U_ELEMS];
__device__ float g_agg_i[(size_t)AGG_I_ELEMS];
__device__ unsigned char g_flag_u[NU];
__device__ unsigned char g_flag_i[NI];

static inline unsigned cdiv(long long a, long long b) { return (unsigned)((a + b - 1) / b); }

// ---------------------------------------------------------------------------
// K0: clear flags (uint4 stores; tiny)
// ---------------------------------------------------------------------------
__global__ void __launch_bounds__(256) k_clear_flags() {
    const int NF_U = NU / 16;                    // 6250 uint4
    const int NF_I = NI / 16;                    // 3125 uint4
    int t = blockIdx.x * blockDim.x + threadIdx.x;
    const uint4 uz = {0u, 0u, 0u, 0u};
    if (t < NF_U)             reinterpret_cast<uint4*>(g_flag_u)[t] = uz;
    else if (t < NF_U + NF_I) reinterpret_cast<uint4*>(g_flag_i)[t - NF_U] = uz;
}

// ---------------------------------------------------------------------------
// K1: mark needed destination rows
// ---------------------------------------------------------------------------
__global__ void __launch_bounds__(256) k_flags(const int* __restrict__ ui,
                                               const int* __restrict__ ii,
                                               const int* __restrict__ ni) {
    int t = blockIdx.x * blockDim.x + threadIdx.x;
    if (t < BATCH)            g_flag_u[ui[t]] = 1;
    else if (t < 2 * BATCH)   g_flag_i[ii[t - BATCH]] = 1;
    else if (t < 3 * BATCH)   g_flag_i[ni[t - 2 * BATCH]] = 1;
}

// ---------------------------------------------------------------------------
// K2: conditionally zero accumulator rows that will actually be used.
//     One thread per (path-row, float4-chunk); early-exit on unflagged rows.
// ---------------------------------------------------------------------------
__global__ void __launch_bounds__(256) k_zero_rows() {
    const long long ROWS_U = (long long)NP * NU; // 300k
    const long long ROWS_I = (long long)NP * NI; // 150k
    long long t = (long long)blockIdx.x * blockDim.x + threadIdx.x;
    long long pr = t >> 4;                       // path-row instance
    int chunk = (int)t & 15;
    const float4 z4 = {0.f, 0.f, 0.f, 0.f};
    if (pr < ROWS_U) {
        int r = (int)(pr % NU);
        if (!g_flag_u[r]) return;
        reinterpret_cast<float4*>(g_agg_u + pr * D)[chunk] = z4;
    } else if (pr < ROWS_U + ROWS_I) {
        long long q = pr - ROWS_U;
        int r = (int)(q % NI);
        if (!g_flag_i[r]) return;
        reinterpret_cast<float4*>(g_agg_i + q * D)[chunk] = z4;
    }
}

// ---------------------------------------------------------------------------
// K3: filtered COO scatter.  16 threads per edge; each thread moves one float4
//     of the table row into the accumulator with red.global.add.v4.f32.
//     Edges whose destination row is not needed are skipped entirely.
// ---------------------------------------------------------------------------
template <bool USERB>
__global__ void __launch_bounds__(256) k_scatter(const float* __restrict__ table,
                                                 const int*   __restrict__ rows,
                                                 const int*   __restrict__ cols,
                                                 const float* __restrict__ vals) {
    constexpr int E  = USERB ? EU : EI;
    constexpr int NR = USERB ? NU : NI;
    const unsigned char* flags = USERB ? g_flag_u : g_flag_i;
    float* agg = USERB ? g_agg_u : g_agg_i;

    long long t = (long long)blockIdx.x * blockDim.x + threadIdx.x;
    int edge = (int)(t >> 4);
    if (edge >= NP * E) return;

    int r = __ldg(rows + edge);
    if (!flags[r]) return;                       // destination row never read

    int   c = __ldg(cols + edge);
    float v = __ldg(vals + edge);
    int   p = edge / E;                          // compile-time divisor -> mul/shift
    int   chunk = (int)t & 15;

    float4 s = __ldg(reinterpret_cast<const float4*>(table + (size_t)c * D) + chunk);
    float* dst = agg + ((size_t)p * NR + r) * D + (size_t)chunk * 4;
    asm volatile("red.global.add.v4.f32 [%0], {%1, %2, %3, %4};"
                 :: "l"(dst), "f"(s.x * v), "f"(s.y * v), "f"(s.z * v), "f"(s.w * v)
                 : "memory");
}

// ---------------------------------------------------------------------------
// K4: epilogue.  out[seg][b] = relu( sum_p wb[p] * relu( agg_p[idx[b]] @ W_p ) )
//     computed only at gathered rows.  W (3x64x64, 48KB) in smem; one warp per
//     row, each lane owns output columns (lane, lane+32); a-vector broadcast
//     via shuffles.
// ---------------------------------------------------------------------------
__global__ void __launch_bounds__(256) k_out(const float* __restrict__ Wu,
                                             const float* __restrict__ Wi,
                                             const float* __restrict__ wb1,
                                             const float* __restrict__ wb2,
                                             const int*   __restrict__ ui,
                                             const int*   __restrict__ ii,
                                             const int*   __restrict__ ni,
                                             float*       __restrict__ out) {
    __shared__ float Ws[NP * D * D];             // 49152 bytes

    constexpr int ROWS_PER_BLOCK = 128;          // 8 warps x 16 rows
    constexpr int BLK_PER_SEG = BATCH / ROWS_PER_BLOCK;  // 64
    int seg = blockIdx.x / BLK_PER_SEG;
    int blk = blockIdx.x % BLK_PER_SEG;

    const float* W   = (seg == 0) ? Wu  : Wi;
    const float* wbp = (seg == 0) ? wb1 : wb2;
    const int*   idxA = (seg == 0) ? ui : ((seg == 1) ? ii : ni);
    const float* agg = (seg == 0) ? g_agg_u : g_agg_i;
    const long long NR = (seg == 0) ? NU : NI;

    for (int j = threadIdx.x; j < NP * D * D; j += blockDim.x) Ws[j] = __ldg(W + j);
    float w0 = __ldg(wbp + 0), w1 = __ldg(wbp + 1), w2 = __ldg(wbp + 2);
    __syncthreads();

    int warp = threadIdx.x >> 5;
    int lane = threadIdx.x & 31;

    for (int i = 0; i < 16; i++) {
        int b = blk * ROWS_PER_BLOCK + warp * 16 + i;
        int idx = __ldg(idxA + b);
        float accL = 0.f, accH = 0.f;
        #pragma unroll
        for (int p = 0; p < NP; p++) {
            const float* arow = agg + ((size_t)p * NR + idx) * D;
            float aL = arow[lane];
            float aH = arow[lane + 32];
            float mL = 0.f, mH = 0.f;
            const float* Wp = Ws + p * D * D;
            #pragma unroll
            for (int d = 0; d < 32; d++) {
                float ad = __shfl_sync(0xffffffffu, aL, d);
                mL += ad * Wp[d * D + lane];
                mH += ad * Wp[d * D + lane + 32];
            }
            #pragma unroll
            for (int d = 0; d < 32; d++) {
                float ad = __shfl_sync(0xffffffffu, aH, d);
                mL += ad * Wp[(d + 32) * D + lane];
                mH += ad * Wp[(d + 32) * D + lane + 32];
            }
            float wp = (p == 0) ? w0 : ((p == 1) ? w1 : w2);
            accL += wp * fmaxf(mL, 0.f);
            accH += wp * fmaxf(mH, 0.f);
        }
        float* o = out + ((size_t)seg * BATCH + b) * D;
        o[lane]      = fmaxf(accL, 0.f);
        o[lane + 32] = fmaxf(accH, 0.f);
    }
}

// ---------------------------------------------------------------------------
// Launch
// ---------------------------------------------------------------------------
extern "C" void kernel_launch(void* const* d_in, const int* in_sizes, int n_in,
                              void* d_out, int out_size) {
    const float* user_table = (const float*)d_in[0];
    const float* item_table = (const float*)d_in[1];
    const float* Wu         = (const float*)d_in[2];
    const float* Wi         = (const float*)d_in[3];
    const float* wb1        = (const float*)d_in[4];
    const float* wb2        = (const float*)d_in[5];
    const float* user_vals  = (const float*)d_in[6];
    const float* item_vals  = (const float*)d_in[7];
    const int*   user_rows  = (const int*)d_in[8];
    const int*   user_cols  = (const int*)d_in[9];
    const int*   item_rows  = (const int*)d_in[10];
    const int*   item_cols  = (const int*)d_in[11];
    const int*   user_idx   = (const int*)d_in[12];
    const int*   item_idx   = (const int*)d_in[13];
    const int*   neg_idx    = (const int*)d_in[14];
    float* out = (float*)d_out;

    k_clear_flags<<<cdiv(NU / 16 + NI / 16, 256), 256>>>();
    k_flags<<<cdiv(3 * BATCH, 256), 256>>>(user_idx, item_idx, neg_idx);
    k_zero_rows<<<cdiv(((long long)NP * NU + (long long)NP * NI) * 16, 256), 256>>>();
    k_scatter<true ><<<cdiv((long long)NP * EU * 16, 256), 256>>>(user_table, user_rows, user_cols, user_vals);
    k_scatter<false><<<cdiv((long long)NP * EI * 16, 256), 256>>>(item_table, item_rows, item_cols, item_vals);
    k_out<<<3 * (BATCH / 128), 256>>>(Wu, Wi, wb1, wb2, user_idx, item_idx, neg_idx, out);
}

// round 3
// speedup vs baseline: 2.8556x; 2.8556x over previous
#include <cuda_runtime.h>
#include <cstdint>

// Problem constants (fixed by the reference).
static constexpr int NU    = 100000;   // users
static constexpr int NI    = 50000;    // items
static constexpr int D     = 64;       // dim
static constexpr int NP    = 3;        // meta-paths
static constexpr int DEG   = 16;
static constexpr int EU    = NU * DEG; // edges per user path (1.6M)
static constexpr int EI    = NI * DEG; // edges per item path (0.8M)
static constexpr int BATCH = 8192;

static constexpr long long AGG_U_ELEMS = (long long)NP * NU * D; // 19.2M
static constexpr long long AGG_I_ELEMS = (long long)NP * NI * D; //  9.6M

__device__ float g_agg_u[(size_t)AGG_U_ELEMS];
__device__ float g_agg_i[(size_t)AGG_I_ELEMS];
__device__ unsigned char g_flag_u[NU];
__device__ unsigned char g_flag_i[NI];

static inline unsigned cdiv(long long a, long long b) { return (unsigned)((a + b - 1) / b); }

// ---------------------------------------------------------------------------
// K0: clear flags
// ---------------------------------------------------------------------------
__global__ void __launch_bounds__(256) k_clear_flags() {
    const int NF_U = NU / 16, NF_I = NI / 16;
    int t = blockIdx.x * blockDim.x + threadIdx.x;
    const uint4 uz = {0u, 0u, 0u, 0u};
    if (t < NF_U)             reinterpret_cast<uint4*>(g_flag_u)[t] = uz;
    else if (t < NF_U + NF_I) reinterpret_cast<uint4*>(g_flag_i)[t - NF_U] = uz;
}

// ---------------------------------------------------------------------------
// K1: mark needed destination rows
// ---------------------------------------------------------------------------
__global__ void __launch_bounds__(256) k_flags(const int* __restrict__ ui,
                                               const int* __restrict__ ii,
                                               const int* __restrict__ ni) {
    int t = blockIdx.x * blockDim.x + threadIdx.x;
    if (t < BATCH)            g_flag_u[ui[t]] = 1;
    else if (t < 2 * BATCH)   g_flag_i[ii[t - BATCH]] = 1;
    else if (t < 3 * BATCH)   g_flag_i[ni[t - 2 * BATCH]] = 1;
}

// ---------------------------------------------------------------------------
// K2: conditionally zero accumulator rows that will be used.
// ---------------------------------------------------------------------------
__global__ void __launch_bounds__(256) k_zero_rows() {
    const long long ROWS_U = (long long)NP * NU;
    const long long ROWS_I = (long long)NP * NI;
    long long t = (long long)blockIdx.x * blockDim.x + threadIdx.x;
    long long pr = t >> 4;
    int chunk = (int)t & 15;
    const float4 z4 = {0.f, 0.f, 0.f, 0.f};
    if (pr < ROWS_U) {
        int r = (int)(pr % NU);
        if (!g_flag_u[r]) return;
        reinterpret_cast<float4*>(g_agg_u + pr * D)[chunk] = z4;
    } else if (pr < ROWS_U + ROWS_I) {
        long long q = pr - ROWS_U;
        int r = (int)(q % NI);
        if (!g_flag_i[r]) return;
        reinterpret_cast<float4*>(g_agg_i + q * D)[chunk] = z4;
    }
}

// ---------------------------------------------------------------------------
// K3: warp-ballot filtered COO scatter.
//   Phase A: one LANE per edge loads (row, col, val) coalesced + flag check.
//   Phase B: survivors processed 2-at-a-time: each half-warp does one edge as
//            16 x (LDG.128 gather  ->  red.global.add.v4.f32).
// ---------------------------------------------------------------------------
template <bool USERB>
__global__ void __launch_bounds__(256) k_scatter(const float* __restrict__ table,
                                                 const int*   __restrict__ rows,
                                                 const int*   __restrict__ cols,
                                                 const float* __restrict__ vals) {
    constexpr int E  = USERB ? EU : EI;
    constexpr int NR = USERB ? NU : NI;
    constexpr int ITER = 4;
    constexpr long long TOTAL = (long long)NP * E;
    const unsigned char* flags = USERB ? g_flag_u : g_flag_i;
    float* agg = USERB ? g_agg_u : g_agg_i;

    const int lane = threadIdx.x & 31;
    const int sub  = lane & 15;            // position within half-warp
    const int half = lane >> 4;            // which half-warp
    const long long wbase =
        ((long long)blockIdx.x * (blockDim.x >> 5) + (threadIdx.x >> 5)) * (32LL * ITER);
    if (wbase >= TOTAL) return;

    // ---- Phase A: metadata loads with full MLP ----
    int   r[ITER], c[ITER], rowidx[ITER];
    float v[ITER];
    bool  inb[ITER], ok[ITER];
    #pragma unroll
    for (int it = 0; it < ITER; it++) {
        long long e = wbase + it * 32 + lane;
        inb[it] = (e < TOTAL);
        long long ec = inb[it] ? e : 0;
        r[it] = __ldg(rows + ec);
        c[it] = __ldg(cols + ec);
        v[it] = __ldg(vals + ec);
        rowidx[it] = (int)(ec / E) * NR + r[it];
    }
    #pragma unroll
    for (int it = 0; it < ITER; it++)
        ok[it] = inb[it] && (flags[r[it]] != 0);

    // ---- Phase B: cooperative survivor processing ----
    #pragma unroll
    for (int it = 0; it < ITER; it++) {
        unsigned m = __ballot_sync(0xffffffffu, ok[it]);
        while (m) {
            int srcA = __ffs(m) - 1; m &= m - 1;
            int srcB = m ? (__ffs(m) - 1) : -1;
            if (srcB >= 0) m &= m - 1;
            int src = half ? srcB : srcA;
            bool active = (src >= 0);
            int srcX = active ? src : 0;
            int   ri = __shfl_sync(0xffffffffu, rowidx[it], srcX);
            int   cc = __shfl_sync(0xffffffffu, c[it],      srcX);
            float vv = __shfl_sync(0xffffffffu, v[it],      srcX);
            if (active) {
                float4 s = __ldg(reinterpret_cast<const float4*>(table + (size_t)cc * D) + sub);
                float* dst = agg + (size_t)ri * D + (size_t)sub * 4;
                asm volatile("red.global.add.v4.f32 [%0], {%1, %2, %3, %4};"
                             :: "l"(dst), "f"(s.x * vv), "f"(s.y * vv),
                                "f"(s.z * vv), "f"(s.w * vv)
                             : "memory");
            }
        }
    }
}

// ---------------------------------------------------------------------------
// K4: epilogue.  out[seg][b] = relu( sum_p wb[p] * relu( agg_p[idx[b]] @ W_p ) )
// ---------------------------------------------------------------------------
__global__ void __launch_bounds__(256) k_out(const float* __restrict__ Wu,
                                             const float* __restrict__ Wi,
                                             const float* __restrict__ wb1,
                                             const float* __restrict__ wb2,
                                             const int*   __restrict__ ui,
                                             const int*   __restrict__ ii,
                                             const int*   __restrict__ ni,
                                             float*       __restrict__ out) {
    __shared__ float Ws[NP * D * D];             // 48 KB

    constexpr int ROWS_PER_BLOCK = 128;
    constexpr int BLK_PER_SEG = BATCH / ROWS_PER_BLOCK;  // 64
    int seg = blockIdx.x / BLK_PER_SEG;
    int blk = blockIdx.x % BLK_PER_SEG;

    const float* W   = (seg == 0) ? Wu  : Wi;
    const float* wbp = (seg == 0) ? wb1 : wb2;
    const int*   idxA = (seg == 0) ? ui : ((seg == 1) ? ii : ni);
    const float* agg = (seg == 0) ? g_agg_u : g_agg_i;
    const long long NR = (seg == 0) ? NU : NI;

    for (int j = threadIdx.x; j < NP * D * D; j += blockDim.x) Ws[j] = __ldg(W + j);
    float w0 = __ldg(wbp + 0), w1 = __ldg(wbp + 1), w2 = __ldg(wbp + 2);
    __syncthreads();

    int warp = threadIdx.x >> 5;
    int lane = threadIdx.x & 31;

    for (int i = 0; i < 16; i++) {
        int b = blk * ROWS_PER_BLOCK + warp * 16 + i;
        int idx = __ldg(idxA + b);
        float accL = 0.f, accH = 0.f;
        #pragma unroll
        for (int p = 0; p < NP; p++) {
            const float* arow = agg + ((size_t)p * NR + idx) * D;
            float aL = arow[lane];
            float aH = arow[lane + 32];
            float mL = 0.f, mH = 0.f;
            const float* Wp = Ws + p * D * D;
            #pragma unroll
            for (int d = 0; d < 32; d++) {
                float ad = __shfl_sync(0xffffffffu, aL, d);
                mL += ad * Wp[d * D + lane];
                mH += ad * Wp[d * D + lane + 32];
            }
            #pragma unroll
            for (int d = 0; d < 32; d++) {
                float ad = __shfl_sync(0xffffffffu, aH, d);
                mL += ad * Wp[(d + 32) * D + lane];
                mH += ad * Wp[(d + 32) * D + lane + 32];
            }
            float wp = (p == 0) ? w0 : ((p == 1) ? w1 : w2);
            accL += wp * fmaxf(mL, 0.f);
            accH += wp * fmaxf(mH, 0.f);
        }
        float* o = out + ((size_t)seg * BATCH + b) * D;
        o[lane]      = fmaxf(accL, 0.f);
        o[lane + 32] = fmaxf(accH, 0.f);
    }
}

// ---------------------------------------------------------------------------
// Launch
// ---------------------------------------------------------------------------
extern "C" void kernel_launch(void* const* d_in, const int* in_sizes, int n_in,
                              void* d_out, int out_size) {
    const float* user_table = (const float*)d_in[0];
    const float* item_table = (const float*)d_in[1];
    const float* Wu         = (const float*)d_in[2];
    const float* Wi         = (const float*)d_in[3];
    const float* wb1        = (const float*)d_in[4];
    const float* wb2        = (const float*)d_in[5];
    const float* user_vals  = (const float*)d_in[6];
    const float* item_vals  = (const float*)d_in[7];
    const int*   user_rows  = (const int*)d_in[8];
    const int*   user_cols  = (const int*)d_in[9];
    const int*   item_rows  = (const int*)d_in[10];
    const int*   item_cols  = (const int*)d_in[11];
    const int*   user_idx   = (const int*)d_in[12];
    const int*   item_idx   = (const int*)d_in[13];
    const int*   neg_idx    = (const int*)d_in[14];
    float* out = (float*)d_out;

    k_clear_flags<<<cdiv(NU / 16 + NI / 16, 256), 256>>>();
    k_flags<<<cdiv(3 * BATCH, 256), 256>>>(user_idx, item_idx, neg_idx);
    k_zero_rows<<<cdiv(((long long)NP * (NU + NI)) * 16, 256), 256>>>();
    // each 256-thread block covers 8 warps * 128 edges = 1024 edges
    k_scatter<true ><<<cdiv((long long)NP * EU, 1024), 256>>>(user_table, user_rows, user_cols, user_vals);
    k_scatter<false><<<cdiv((long long)NP * EI, 1024), 256>>>(item_table, item_rows, item_cols, item_vals);
    k_out<<<3 * (BATCH / 128), 256>>>(Wu, Wi, wb1, wb2, user_idx, item_idx, neg_idx, out);
}

// round 6
// speedup vs baseline: 2.9205x; 1.0227x over previous
#include <cuda_runtime.h>
#include <cstdint>

// Problem constants (fixed by the reference).
static constexpr int NU    = 100000;   // users
static constexpr int NI    = 50000;    // items
static constexpr int D     = 64;       // dim
static constexpr int NP    = 3;        // meta-paths
static constexpr int DEG   = 16;
static constexpr int EU    = NU * DEG; // edges per user path (1.6M)
static constexpr int EI    = NI * DEG; // edges per item path (0.8M)
static constexpr int BATCH = 8192;

static constexpr int MAXROWS  = 3 * BATCH;        // 24576 distinct flagged rows max
static constexpr int MAXSLOTS = MAXROWS * NP;     // 73728 (id, path) slots
static constexpr int CAP      = 64;               // max edges per slot bin

// Scratch (static device memory; ~58 MB total).
__device__ float              g_agg[(size_t)MAXSLOTS * D];    // 18.9 MB (compact)
__device__ unsigned long long g_bin[(size_t)MAXSLOTS * CAP];  // 37.7 MB (compact)
__device__ int                g_cnt[MAXSLOTS];                // 295 KB
__device__ int                g_rowid[NU + NI];               // 600 KB (-1 = not live)
__device__ int                g_live[MAXROWS];                // r | (item<<30)
__device__ int                g_nlive;

static inline unsigned cdiv(long long a, long long b) { return (unsigned)((a + b - 1) / b); }

// ---------------------------------------------------------------------------
// K0: clear rowid map, bin cursors, live counter
// ---------------------------------------------------------------------------
__global__ void __launch_bounds__(256) k_clear() {
    int t = blockIdx.x * blockDim.x + threadIdx.x;
    if (t < NU + NI) g_rowid[t] = -1;
    int c = t - (NU + NI);
    if (c >= 0 && c < MAXSLOTS) g_cnt[c] = 0;
    if (t == 0) g_nlive = 0;
}

// ---------------------------------------------------------------------------
// K1: flag rows + assign compact ids (CAS-claim, winner takes an id)
// ---------------------------------------------------------------------------
__global__ void __launch_bounds__(256) k_flags(const int* __restrict__ ui,
                                               const int* __restrict__ ii,
                                               const int* __restrict__ ni) {
    int t = blockIdx.x * blockDim.x + threadIdx.x;
    int rg, tag;
    if (t < BATCH)          { rg = ui[t];               tag = 0; }
    else if (t < 2 * BATCH) { rg = NU + ii[t - BATCH];  tag = 1 << 30; }
    else if (t < 3 * BATCH) { rg = NU + ni[t - 2*BATCH];tag = 1 << 30; }
    else return;

    if (atomicCAS(&g_rowid[rg], -1, -2) == -1) {
        int id = atomicAdd(&g_nlive, 1);
        g_live[id] = (tag ? (rg - NU) : rg) | tag;
        g_rowid[rg] = id;
    }
}

// ---------------------------------------------------------------------------
// K2: bin pass.  Streams all edge metadata once; survivors (live destination
//     row) drop packed (val,col) into compact bin slot = id*NP + path.
// ---------------------------------------------------------------------------
__global__ void __launch_bounds__(256) k_bin(const int*   __restrict__ u_rows,
                                             const int*   __restrict__ u_cols,
                                             const float* __restrict__ u_vals,
                                             const int*   __restrict__ i_rows,
                                             const int*   __restrict__ i_cols,
                                             const float* __restrict__ i_vals) {
    constexpr int ITER = 2;
    constexpr long long TOTAL = (long long)NP * (EU + EI);
    long long t0 = ((long long)blockIdx.x * blockDim.x) * ITER + threadIdx.x;

    #pragma unroll
    for (int it = 0; it < ITER; it++) {
        long long t = t0 + (long long)it * blockDim.x;
        if (t >= TOTAL) return;
        int id, p, c; float v;
        if (t < (long long)NP * EU) {
            int e = (int)t;
            int r = __ldg(u_rows + e);
            id = g_rowid[r];
            if (id < 0) continue;
            p = e / EU;
            c = __ldg(u_cols + e);
            v = __ldg(u_vals + e);
        } else {
            int e = (int)(t - (long long)NP * EU);
            int r = __ldg(i_rows + e);
            id = g_rowid[NU + r];
            if (id < 0) continue;
            p = e / EI;
            c = __ldg(i_cols + e);
            v = __ldg(i_vals + e);
        }
        int slot = id * NP + p;
        int pos = atomicAdd(&g_cnt[slot], 1);
        if (pos < CAP) {
            unsigned long long pk =
                ((unsigned long long)__float_as_uint(v) << 32) | (unsigned)c;
            g_bin[(size_t)slot * CAP + pos] = pk;
        }
    }
}

// ---------------------------------------------------------------------------
// K3: per-slot reduction.  One warp per live (id,path) slot; register
//     accumulation (float2/lane), single 256B store.  No atomics, no zeroing.
// ---------------------------------------------------------------------------
__global__ void __launch_bounds__(128) k_process(const float* __restrict__ u_table,
                                                 const float* __restrict__ i_table) {
    int slot = blockIdx.x * (blockDim.x >> 5) + (threadIdx.x >> 5);
    if (slot >= MAXSLOTS) return;
    int id = slot / NP;
    if (id >= g_nlive) return;
    int lane = threadIdx.x & 31;

    int packed = g_live[id];
    bool item = (packed >> 30) & 1;
    const float* table = item ? i_table : u_table;

    int n = min(g_cnt[slot], CAP);
    const unsigned long long* bin = g_bin + (size_t)slot * CAP;

    float2 acc = {0.f, 0.f};
    int k = 0;
    for (; k + 1 < n; k += 2) {
        unsigned long long pA = __ldg(bin + k);
        unsigned long long pB = __ldg(bin + k + 1);
        int   cA = (int)(pA & 0x3FFFFFFFull);
        int   cB = (int)(pB & 0x3FFFFFFFull);
        float vA = __uint_as_float((unsigned)(pA >> 32));
        float vB = __uint_as_float((unsigned)(pB >> 32));
        float2 tA = __ldg(reinterpret_cast<const float2*>(table + (size_t)cA * D) + lane);
        float2 tB = __ldg(reinterpret_cast<const float2*>(table + (size_t)cB * D) + lane);
        acc.x += vA * tA.x; acc.y += vA * tA.y;
        acc.x += vB * tB.x; acc.y += vB * tB.y;
    }
    if (k < n) {
        unsigned long long p = __ldg(bin + k);
        int   c = (int)(p & 0x3FFFFFFFull);
        float v = __uint_as_float((unsigned)(p >> 32));
        float2 tv = __ldg(reinterpret_cast<const float2*>(table + (size_t)c * D) + lane);
        acc.x += v * tv.x; acc.y += v * tv.y;
    }
    reinterpret_cast<float2*>(g_agg + (size_t)slot * D)[lane] = acc;
}

// ---------------------------------------------------------------------------
// K4: epilogue.  out[seg][b] = relu( sum_p wb[p] * relu( agg[id,p] @ W_p ) )
// ---------------------------------------------------------------------------
__global__ void __launch_bounds__(256) k_out(const float* __restrict__ Wu,
                                             const float* __restrict__ Wi,
                                             const float* __restrict__ wb1,
                                             const float* __restrict__ wb2,
                                             const int*   __restrict__ ui,
                                             const int*   __restrict__ ii,
                                             const int*   __restrict__ ni,
                                             float*       __restrict__ out) {
    __shared__ float Ws[NP * D * D];             // 48 KB

    constexpr int ROWS_PER_BLOCK = 128;
    constexpr int BLK_PER_SEG = BATCH / ROWS_PER_BLOCK;  // 64
    int seg = blockIdx.x / BLK_PER_SEG;
    int blk = blockIdx.x % BLK_PER_SEG;

    const float* W    = (seg == 0) ? Wu  : Wi;
    const float* wbp  = (seg == 0) ? wb1 : wb2;
    const int*   idxA = (seg == 0) ? ui : ((seg == 1) ? ii : ni);
    const int    roff = (seg == 0) ? 0 : NU;

    for (int j = threadIdx.x; j < NP * D * D; j += blockDim.x) Ws[j] = __ldg(W + j);
    float w0 = __ldg(wbp + 0), w1 = __ldg(wbp + 1), w2 = __ldg(wbp + 2);
    __syncthreads();

    int warp = threadIdx.x >> 5;
    int lane = threadIdx.x & 31;

    for (int i = 0; i < 16; i++) {
        int b = blk * ROWS_PER_BLOCK + warp * 16 + i;
        int idx = __ldg(idxA + b);
        int id = g_rowid[roff + idx];            // compact id (always >= 0)
        float accL = 0.f, accH = 0.f;
        #pragma unroll
        for (int p = 0; p < NP; p++) {
            const float* arow = g_agg + (size_t)(id * NP + p) * D;
            float aL = arow[lane];
            float aH = arow[lane + 32];
            float mL = 0.f, mH = 0.f;
            const float* Wp = Ws + p * D * D;
            #pragma unroll
            for (int d = 0; d < 32; d++) {
                float ad = __shfl_sync(0xffffffffu, aL, d);
                mL += ad * Wp[d * D + lane];
                mH += ad * Wp[d * D + lane + 32];
            }
            #pragma unroll
            for (int d = 0; d < 32; d++) {
                float ad = __shfl_sync(0xffffffffu, aH, d);
                mL += ad * Wp[(d + 32) * D + lane];
                mH += ad * Wp[(d + 32) * D + lane + 32];
            }
            float wp = (p == 0) ? w0 : ((p == 1) ? w1 : w2);
            accL += wp * fmaxf(mL, 0.f);
            accH += wp * fmaxf(mH, 0.f);
        }
        float* o = out + ((size_t)seg * BATCH + b) * D;
        o[lane]      = fmaxf(accL, 0.f);
        o[lane + 32] = fmaxf(accH, 0.f);
    }
}

// ---------------------------------------------------------------------------
// Launch
// ---------------------------------------------------------------------------
extern "C" void kernel_launch(void* const* d_in, const int* in_sizes, int n_in,
                              void* d_out, int out_size) {
    const float* user_table = (const float*)d_in[0];
    const float* item_table = (const float*)d_in[1];
    const float* Wu         = (const float*)d_in[2];
    const float* Wi         = (const float*)d_in[3];
    const float* wb1        = (const float*)d_in[4];
    const float* wb2        = (const float*)d_in[5];
    const float* user_vals  = (const float*)d_in[6];
    const float* item_vals  = (const float*)d_in[7];
    const int*   user_rows  = (const int*)d_in[8];
    const int*   user_cols  = (const int*)d_in[9];
    const int*   item_rows  = (const int*)d_in[10];
    const int*   item_cols  = (const int*)d_in[11];
    const int*   user_idx   = (const int*)d_in[12];
    const int*   item_idx   = (const int*)d_in[13];
    const int*   neg_idx    = (const int*)d_in[14];
    float* out = (float*)d_out;

    k_clear<<<cdiv(NU + NI + MAXSLOTS, 256), 256>>>();
    k_flags<<<cdiv(3 * BATCH, 256), 256>>>(user_idx, item_idx, neg_idx);
    k_bin<<<cdiv((long long)NP * (EU + EI), 512), 256>>>(user_rows, user_cols, user_vals,
                                                         item_rows, item_cols, item_vals);
    k_process<<<cdiv(MAXSLOTS, 4), 128>>>(user_table, item_table);
    k_out<<<3 * (BATCH / 128), 256>>>(Wu, Wi, wb1, wb2, user_idx, item_idx, neg_idx, out);
}